// round 15
// baseline (speedup 1.0000x reference)
#include <cuda_runtime.h>
#include <cuda_bf16.h>
#include <cstdint>

// ---------------------------------------------------------------------------
// MultiheadLocalAttentionV1: N=2, C=256, H=8, HD=32, 32x32 spatial,
// 15x15 window (225 taps), dilation 1, pad 7.
//
//   prep_all   : weight/qkv bf16-split fragments, T*Wrk B-fragments, rel_v^T
//   proj_gemm  : split-K x4 bf16 mma GEMM; K pre-split bf16
//   attn_kernel: MMA logits + fp32 softmax + SIMT sliding-window output,
//                epilogue scatters into final-GEMM A-fragments
//   final_gemm : split-K x4 bf16 mma GEMM, out = ao @ Wp^T + bp
// ---------------------------------------------------------------------------

#define NB      2
#define HNUM    8
#define HDim    32
#define CCH     256
#define WDIM    32
#define HW      1024
#define WS      15
#define WS2     225
#define MAXDIS  7

#define TW      8
#define TH      4
#define TPIX    32
#define HR      (TH + 14)   // 18
#define HC      (TW + 14)   // 22
#define NHALO   (HR * HC)   // 396
#define NHALO_P 400
#define KSTR    36
#define ASTR    244
#define QSTR    33
#define KROWU   18

#define T_CONST 5.656854249492381f
#define INV_T   0.17677669529663689f

#define OUT_ELEMS  (HW * NB * CCH)
#define ATTN_ELEMS (NB * HNUM * WS2 * HW)

// attn smem layout (bytes)
#define SM_K    0
#define SM_KLO_U 7200
#define SM_A    57600
#define SM_Q    88832
#define SMEM_ATTN 93056

#define AFRAGS  65536
#define BFRAGS  16384

// -------------------------- global scratch ---------------------------------
__device__ float g_qs[NB * HNUM * HW * HDim];
__device__ float g_vp[NB * HNUM * HW * HDim];
__device__ float g_rvT[HNUM * WS2 * HDim];
__device__ uint32_t g_kbf_hi[NB * HNUM * HW * 16];
__device__ uint32_t g_kbf_lo[NB * HNUM * HW * 16];

__device__ uint4 g_Ahi[4 * AFRAGS];   // slots: 0=q 1=k 2=v 3=ao
__device__ uint4 g_Alo[4 * AFRAGS];
__device__ uint2 g_Bhi[4 * BFRAGS];   // slots: 0=WQ 1=WK 2=WV 3=Wp
__device__ uint2 g_Blo[4 * BFRAGS];

__device__ uint2 g_WrkFh[HNUM * 30 * 2 * 32];
__device__ uint2 g_WrkFl[HNUM * 30 * 2 * 32];

// ---------------------------------------------------------------------------
// helpers
// ---------------------------------------------------------------------------
__device__ __forceinline__ uint32_t pack2(float a, float b) {
    __nv_bfloat162 t = __floats2bfloat162_rn(a, b);
    return *reinterpret_cast<uint32_t*>(&t);
}
__device__ __forceinline__ void split1(float x, float& hi, float& lo) {
    hi = __bfloat162float(__float2bfloat16(x));
    lo = x - hi;
}
__device__ __forceinline__ void mma_bf16(float* acc, uint4 a, uint2 b) {
    asm volatile(
        "mma.sync.aligned.m16n8k16.row.col.f32.bf16.bf16.f32 "
        "{%0,%1,%2,%3},{%4,%5,%6,%7},{%8,%9},{%0,%1,%2,%3};\n"
        : "+f"(acc[0]), "+f"(acc[1]), "+f"(acc[2]), "+f"(acc[3])
        : "r"(a.x), "r"(a.y), "r"(a.z), "r"(a.w), "r"(b.x), "r"(b.y));
}
__device__ __forceinline__ void mma3(float* acc, uint4 ah, uint4 al,
                                     uint2 bh, uint2 bl) {
    mma_bf16(acc, ah, bh);
    mma_bf16(acc, ah, bl);
    mma_bf16(acc, al, bh);
}

// ---------------------------------------------------------------------------
// prep_all: [0,256) weights; [256,1024) q/k/v; [1024,1084) T*Wrk frags;
//           [1084,1309) rel_v transpose
// ---------------------------------------------------------------------------
__global__ __launch_bounds__(256) void prep_all(
    const float* __restrict__ q, const float* __restrict__ k,
    const float* __restrict__ v,
    const float* __restrict__ WQ, const float* __restrict__ WK,
    const float* __restrict__ WV, const float* __restrict__ Wp,
    const float* __restrict__ Wrk, const float* __restrict__ rel_v)
{
    const int b = blockIdx.x;

    if (b < 256) {
        int tid  = b * 256 + threadIdx.x;
        int lane = tid & 31;
        int k16  = (tid >> 5) & 15;
        int n8   = (tid >> 9) & 31;
        int mat  = tid >> 14;
        const float* W = (mat == 0) ? WQ : (mat == 1) ? WK : (mat == 2) ? WV : Wp;

        int g = lane >> 2, tig = lane & 3;
        int n  = n8 * 8 + g;
        int kb = k16 * 16 + 2 * tig;

        const float* r = W + (size_t)n * 256;
        float h0, l0, h1, l1, h8, l8, h9, l9;
        split1(r[kb],     h0, l0);
        split1(r[kb + 1], h1, l1);
        split1(r[kb + 8], h8, l8);
        split1(r[kb + 9], h9, l9);

        size_t idx = ((size_t)(mat * 32 + n8) * 16 + k16) * 32 + lane;
        g_Bhi[idx] = make_uint2(pack2(h0, h1), pack2(h8, h9));
        g_Blo[idx] = make_uint2(pack2(l0, l1), pack2(l8, l9));
    } else if (b < 1024) {
        int mat = (b - 256) >> 8;
        const float* src = (mat == 0) ? q : (mat == 1) ? k : v;

        int tid  = ((b - 256) & 255) * 256 + threadIdx.x;
        int lane = tid & 31;
        int k16  = (tid >> 5) & 15;
        int m16  = tid >> 9;
        int g = lane >> 2, tig = lane & 3;
        int r0 = m16 * 16 + g;
        int r1 = r0 + 8;
        int kb = k16 * 16 + 2 * tig;

        int n0 = r0 >> 10, p0 = r0 & 1023;
        int n1 = r1 >> 10, p1 = r1 & 1023;

        uint32_t hi[4], lo[4];
#pragma unroll
        for (int j = 0; j < 4; j++) {
            int row_n = (j & 1) ? n1 : n0;
            int row_p = (j & 1) ? p1 : p0;
            int kc = kb + ((j >> 1) ? 8 : 0);
            float f0 = src[((size_t)(row_n * 256 + kc)) * 1024 + row_p];
            float f1 = src[((size_t)(row_n * 256 + kc + 1)) * 1024 + row_p];
            float h0, l0, h1, l1;
            split1(f0, h0, l0);
            split1(f1, h1, l1);
            hi[j] = pack2(h0, h1);
            lo[j] = pack2(l0, l1);
        }
        size_t idx = (size_t)mat * AFRAGS + ((size_t)m16 * 16 + k16) * 32 + lane;
        g_Ahi[idx] = make_uint4(hi[0], hi[1], hi[2], hi[3]);
        g_Alo[idx] = make_uint4(lo[0], lo[1], lo[2], lo[3]);
    } else if (b < 1084) {
        int i = (b - 1024) * 256 + threadIdx.x;
        int lane = i & 31;
        int k16  = (i >> 5) & 1;
        int rest = i >> 6;
        int n8 = rest % 30;
        int h  = rest / 30;
        int g = lane >> 2, tig = lane & 3;
        int s240 = n8 * 8 + g;
        int kh = s240 >> 4, kw = s240 & 15;
        int ch = 16 * k16 + 2 * tig;

        float v0 = 0.f, v1 = 0.f, v8 = 0.f, v9 = 0.f;
        if (kw < 15) {
            const float* wr = Wrk + ((size_t)(h * WS2 + kh * WS + kw)) * HDim;
            v0 = T_CONST * wr[ch];
            v1 = T_CONST * wr[ch + 1];
            v8 = T_CONST * wr[ch + 8];
            v9 = T_CONST * wr[ch + 9];
        }
        float h0, l0, h1, l1, h8, l8, h9, l9;
        split1(v0, h0, l0); split1(v1, h1, l1);
        split1(v8, h8, l8); split1(v9, h9, l9);
        size_t idx = ((size_t)(h * 30 + n8) * 2 + k16) * 32 + lane;
        g_WrkFh[idx] = make_uint2(pack2(h0, h1), pack2(h8, h9));
        g_WrkFl[idx] = make_uint2(pack2(l0, l1), pack2(l8, l9));
    } else {
        int i = (b - 1084) * 256 + threadIdx.x;
        if (i < HNUM * WS2 * HDim) {
            int c = i & 31;
            int s = (i >> 5) % WS2;
            int h = i / (WS2 * HDim);
            g_rvT[i] = rel_v[(h * HDim + c) * WS2 + s];
        }
    }
}

// ---------------------------------------------------------------------------
// GEMM quarter-core: warp computes 16m x 16n over 4 k16 steps from k0.
// ---------------------------------------------------------------------------
__device__ __forceinline__ void gemm_core4(
    const uint4* __restrict__ Ahi, const uint4* __restrict__ Alo,
    const uint2* __restrict__ Bhi, const uint2* __restrict__ Blo,
    int m16, int n8b, int lane, int k0, float acc[2][4])
{
#pragma unroll
    for (int kk = 0; kk < 4; kk++) {
        const int k16 = k0 + kk;
        uint4 ah = Ahi[((size_t)m16 * 16 + k16) * 32 + lane];
        uint4 al = Alo[((size_t)m16 * 16 + k16) * 32 + lane];
#pragma unroll
        for (int nt = 0; nt < 2; nt++) {
            size_t bi = ((size_t)(n8b + nt) * 16 + k16) * 32 + lane;
            mma3(acc[nt], ah, al, Bhi[bi], Blo[bi]);
        }
    }
}

// ---------------------------------------------------------------------------
// proj_gemm: split-K x4. grid (64, 8, 3), 512 threads
// (4 tile-warps x 4 k-quarters).
// ---------------------------------------------------------------------------
__global__ __launch_bounds__(512) void proj_gemm(
    const float* __restrict__ bQ, const float* __restrict__ bK,
    const float* __restrict__ bV)
{
    __shared__ float red[4][3][8][32];

    const int mat  = blockIdx.z;
    const int t    = threadIdx.x;
    const int warp = t >> 5;
    const int lane = t & 31;
    const int tile = warp & 3;
    const int kq   = warp >> 2;
    const int m16  = blockIdx.x * 2 + (tile & 1);
    const int n8b  = (blockIdx.y * 2 + (tile >> 1)) * 2;

    const uint4* Ahi = g_Ahi + (size_t)mat * AFRAGS;
    const uint4* Alo = g_Alo + (size_t)mat * AFRAGS;
    const uint2* Bhi = g_Bhi + (size_t)mat * BFRAGS;
    const uint2* Blo = g_Blo + (size_t)mat * BFRAGS;

    float acc[2][4];
#pragma unroll
    for (int i = 0; i < 2; i++)
#pragma unroll
        for (int j = 0; j < 4; j++) acc[i][j] = 0.f;

    gemm_core4(Ahi, Alo, Bhi, Blo, m16, n8b, lane, kq * 4, acc);

    if (kq > 0) {
#pragma unroll
        for (int i = 0; i < 2; i++)
#pragma unroll
            for (int j = 0; j < 4; j++)
                red[tile][kq - 1][i * 4 + j][lane] = acc[i][j];
    }
    __syncthreads();
    if (kq == 0) {
#pragma unroll
        for (int r = 0; r < 3; r++)
#pragma unroll
            for (int i = 0; i < 2; i++)
#pragma unroll
                for (int j = 0; j < 4; j++)
                    acc[i][j] += red[tile][r][i * 4 + j][lane];

        const float* b = (mat == 0) ? bQ : (mat == 1) ? bK : bV;
        const int g = lane >> 2, tig = lane & 3;
        const int r0 = m16 * 16 + g;
#pragma unroll
        for (int nt = 0; nt < 2; nt++) {
            const int o0 = (n8b + nt) * 8 + 2 * tig;
            const int h = o0 >> 5, hd = o0 & 31;
            const float b0 = b[o0], b1 = b[o0 + 1];
#pragma unroll
            for (int rr = 0; rr < 2; rr++) {
                const int r = r0 + rr * 8;
                const int n_b = r >> 10, p = r & 1023;
                float vx = acc[nt][rr * 2]     + b0;
                float vy = acc[nt][rr * 2 + 1] + b1;
                if (mat == 0) {
                    float2 val = make_float2(vx * INV_T, vy * INV_T);
                    *(float2*)&g_qs[((size_t)(n_b * HNUM + h) * HW + p) * HDim + hd] = val;
                } else if (mat == 1) {
                    float hx, lx, hy, ly;
                    split1(vx, hx, lx);
                    split1(vy, hy, ly);
                    size_t u = ((size_t)(n_b * HNUM + h) * HW + p) * 16 + (hd >> 1);
                    g_kbf_hi[u] = pack2(hx, hy);
                    g_kbf_lo[u] = pack2(lx, ly);
                } else {
                    float2 val = make_float2(vx, vy);
                    *(float2*)&g_vp[((size_t)(n_b * HNUM + h) * HW + p) * HDim + hd] = val;
                }
            }
        }
    }
}

// ---------------------------------------------------------------------------
// final_gemm: split-K x4. grid (64, 8), 512 threads.
// ---------------------------------------------------------------------------
__global__ __launch_bounds__(512) void final_gemm(
    const float* __restrict__ bp, float* __restrict__ out)
{
    __shared__ float red[4][3][8][32];

    const int t    = threadIdx.x;
    const int warp = t >> 5;
    const int lane = t & 31;
    const int tile = warp & 3;
    const int kq   = warp >> 2;
    const int m16  = blockIdx.x * 2 + (tile & 1);
    const int n8b  = (blockIdx.y * 2 + (tile >> 1)) * 2;

    const uint4* Ahi = g_Ahi + (size_t)3 * AFRAGS;
    const uint4* Alo = g_Alo + (size_t)3 * AFRAGS;
    const uint2* Bhi = g_Bhi + (size_t)3 * BFRAGS;
    const uint2* Blo = g_Blo + (size_t)3 * BFRAGS;

    float acc[2][4];
#pragma unroll
    for (int i = 0; i < 2; i++)
#pragma unroll
        for (int j = 0; j < 4; j++) acc[i][j] = 0.f;

    gemm_core4(Ahi, Alo, Bhi, Blo, m16, n8b, lane, kq * 4, acc);

    if (kq > 0) {
#pragma unroll
        for (int i = 0; i < 2; i++)
#pragma unroll
            for (int j = 0; j < 4; j++)
                red[tile][kq - 1][i * 4 + j][lane] = acc[i][j];
    }
    __syncthreads();
    if (kq == 0) {
#pragma unroll
        for (int r = 0; r < 3; r++)
#pragma unroll
            for (int i = 0; i < 2; i++)
#pragma unroll
                for (int j = 0; j < 4; j++)
                    acc[i][j] += red[tile][r][i * 4 + j][lane];

        const int g = lane >> 2, tig = lane & 3;
        const int r0 = m16 * 16 + g;
#pragma unroll
        for (int nt = 0; nt < 2; nt++) {
            const int o0 = (n8b + nt) * 8 + 2 * tig;
            const float b0 = bp[o0], b1 = bp[o0 + 1];
#pragma unroll
            for (int rr = 0; rr < 2; rr++) {
                const int r = r0 + rr * 8;
                const int n_b = r >> 10, p = r & 1023;
                float2 val;
                val.x = acc[nt][rr * 2]     + b0;
                val.y = acc[nt][rr * 2 + 1] + b1;
                *(float2*)&out[((size_t)p * NB + n_b) * CCH + o0] = val;
            }
        }
    }
}

// ---------------------------------------------------------------------------
// attn_kernel: grid (32 tiles, 8 heads, 2 batch), 256 threads (8 warps).
// ---------------------------------------------------------------------------
extern __shared__ char smc[];

__global__ __launch_bounds__(256) void attn_kernel(
    const float* __restrict__ brk, float* __restrict__ attn_out)
{
    const int h = blockIdx.y;
    const int n = blockIdx.z;
    const int tileIdx = blockIdx.x;
    const int tx0 = (tileIdx & 3) * TW;
    const int ty0 = (tileIdx >> 2) * TH;
    const int t = threadIdx.x;
    const int w = t >> 5;
    const int lane = t & 31;
    const int g = lane >> 2, tig = lane & 3;
    const int nh = n * HNUM + h;

    uint32_t* kHiU = (uint32_t*)(smc + SM_K);
    uint32_t* kLoU = kHiU + SM_KLO_U;
    float*    vsm  = (float*)(smc + SM_K);
    float*    atsm = (float*)(smc + SM_A);
    float*    sQ   = (float*)(smc + SM_Q);
    float*    sPart = sQ;

    for (int idx = t; idx < TPIX * 32; idx += 256) {
        int px = idx >> 5, c = idx & 31;
        int gp = (ty0 + (px >> 3)) * WDIM + tx0 + (px & 7);
        sQ[px * QSTR + c] = g_qs[((size_t)nh * HW + gp) * HDim + c];
    }
    {
        const uint32_t* kh_hi = g_kbf_hi + (size_t)nh * HW * 16;
        const uint32_t* kh_lo = g_kbf_lo + (size_t)nh * HW * 16;
        for (int idx = t; idx < NHALO_P * 16; idx += 256) {
            int hp = idx >> 4, c2 = idx & 15;
            uint32_t vh = 0, vl = 0;
            if (hp < NHALO) {
                int hy = hp / HC, hx = hp - hy * HC;
                int gy = ty0 - MAXDIS + hy, gx = tx0 - MAXDIS + hx;
                if ((unsigned)gy < 32u && (unsigned)gx < 32u) {
                    size_t off = (size_t)(gy * WDIM + gx) * 16 + c2;
                    vh = kh_hi[off];
                    vl = kh_lo[off];
                }
            }
            kHiU[hp * KROWU + c2] = vh;
            kLoU[hp * KROWU + c2] = vl;
        }
    }
    __syncthreads();

    // ---- build Q A-fragments: 2 m16 x 2 k16 ----
    uint4 aQh[2][2], aQl[2][2];
#pragma unroll
    for (int m16 = 0; m16 < 2; m16++) {
#pragma unroll
        for (int k16 = 0; k16 < 2; k16++) {
            int rb = m16 * 16 + g;
            int kb = 16 * k16 + 2 * tig;
            float v00 = sQ[rb * QSTR + kb],            v01 = sQ[rb * QSTR + kb + 1];
            float v10 = sQ[(rb + 8) * QSTR + kb],      v11 = sQ[(rb + 8) * QSTR + kb + 1];
            float v08 = sQ[rb * QSTR + kb + 8],        v09 = sQ[rb * QSTR + kb + 9];
            float v18 = sQ[(rb + 8) * QSTR + kb + 8],  v19 = sQ[(rb + 8) * QSTR + kb + 9];
            float h00,l00,h01,l01,h10,l10,h11,l11,h08,l08,h09,l09,h18,l18,h19,l19;
            split1(v00,h00,l00); split1(v01,h01,l01);
            split1(v10,h10,l10); split1(v11,h11,l11);
            split1(v08,h08,l08); split1(v09,h09,l09);
            split1(v18,h18,l18); split1(v19,h19,l19);
            aQh[m16][k16] = make_uint4(pack2(h00,h01), pack2(h10,h11),
                                       pack2(h08,h09), pack2(h18,h19));
            aQl[m16][k16] = make_uint4(pack2(l00,l01), pack2(l10,l11),
                                       pack2(l08,l09), pack2(l18,l19));
        }
    }

    // ---- phase R: rel logits GEMM -> atsm ----
    for (int n8 = w; n8 < 30; n8 += 8) {
        float acc[2][4];
#pragma unroll
        for (int i = 0; i < 2; i++)
#pragma unroll
            for (int j = 0; j < 4; j++) acc[i][j] = 0.f;
#pragma unroll
        for (int k16 = 0; k16 < 2; k16++) {
            size_t bi = ((size_t)(h * 30 + n8) * 2 + k16) * 32 + lane;
            uint2 bh = g_WrkFh[bi];
            uint2 bl = g_WrkFl[bi];
            mma3(acc[0], aQh[0][k16], aQl[0][k16], bh, bl);
            mma3(acc[1], aQh[1][k16], aQl[1][k16], bh, bl);
        }
        const int c0 = n8 * 8 + 2 * tig;
        const int kh = c0 >> 4, kw = c0 & 15;
        float bb0 = (kw < 15) ? brk[h * WS2 + kh * WS + kw] : 0.f;
        float bb1 = (kw < 14) ? brk[h * WS2 + kh * WS + kw + 1] : 0.f;
#pragma unroll
        for (int m16 = 0; m16 < 2; m16++) {
            const int rb = m16 * 16 + g;
            atsm[rb * ASTR + c0]           = acc[m16][0] + bb0;
            atsm[rb * ASTR + c0 + 1]       = acc[m16][1] + bb1;
            atsm[(rb + 8) * ASTR + c0]     = acc[m16][2] + bb0;
            atsm[(rb + 8) * ASTR + c0 + 1] = acc[m16][3] + bb1;
        }
    }
    __syncthreads();

    // ---- phase S: dense QK GEMM + banded scatter ----
    for (int n8 = w; n8 < 50; n8 += 8) {
        float acc[2][4];
#pragma unroll
        for (int i = 0; i < 2; i++)
#pragma unroll
            for (int j = 0; j < 4; j++) acc[i][j] = 0.f;
#pragma unroll
        for (int k16 = 0; k16 < 2; k16++) {
            int bi = (n8 * 8 + g) * KROWU + 8 * k16 + tig;
            uint2 bh = make_uint2(kHiU[bi], kHiU[bi + 4]);
            uint2 bl = make_uint2(kLoU[bi], kLoU[bi + 4]);
            mma3(acc[0], aQh[0][k16], aQl[0][k16], bh, bl);
            mma3(acc[1], aQh[1][k16], aQl[1][k16], bh, bl);
        }
        const int c0 = n8 * 8 + 2 * tig;
#pragma unroll
        for (int m16 = 0; m16 < 2; m16++) {
#pragma unroll
            for (int j = 0; j < 4; j++) {
                const int row = m16 * 16 + g + ((j >> 1) ? 8 : 0);
                const int cc  = c0 + (j & 1);
                if (cc < NHALO) {
                    const int hy = cc / HC, hx = cc - hy * HC;
                    const int py = row >> 3, pxx = row & 7;
                    const int kh = hy - py, kw = hx - pxx;
                    if ((unsigned)kh < 15u && (unsigned)kw < 15u) {
                        const int gy = ty0 + hy - MAXDIS;
                        const int gx = tx0 + hx - MAXDIS;
                        const int idx = row * ASTR + kh * 16 + kw;
                        float a = atsm[idx] + acc[m16][j];
                        if (!((unsigned)gy < 32u && (unsigned)gx < 32u))
                            a -= 1e8f;
                        atsm[idx] = a;
                    }
                }
            }
        }
    }
    __syncthreads();

    // ---- load V fp32 (overwrites K region) ----
    for (int i4 = t; i4 < NHALO * 8; i4 += 256) {
        int hp = i4 >> 3, c4 = (i4 & 7) * 4;
        int hy = hp / HC, hx = hp - hy * HC;
        int gy = ty0 - MAXDIS + hy, gx = tx0 - MAXDIS + hx;
        float4 vv = make_float4(0.f, 0.f, 0.f, 0.f);
        if ((unsigned)gy < 32u && (unsigned)gx < 32u)
            vv = *(const float4*)&g_vp[((size_t)nh * HW + gy * WDIM + gx) * HDim + c4];
        *(float4*)&vsm[hp * KSTR + c4] = vv;
    }

    // ---- softmax ----
    {
#pragma unroll
        for (int pp = 0; pp < 4; pp++) {
            const int px = w * 4 + pp;
            float* arow = &atsm[px * ASTR];
            if (lane < 15) arow[lane * 16 + 15] = 0.f;
            float vals[8];
            int   offs[8];
            float mx = -3.4e38f;
#pragma unroll
            for (int i = 0; i < 8; i++) {
                int s = lane + 32 * i;
                if (s < WS2) {
                    offs[i] = (s / WS) * 16 + (s % WS);
                    vals[i] = arow[offs[i]];
                } else { offs[i] = -1; vals[i] = -3.4e38f; }
                mx = fmaxf(mx, vals[i]);
            }
#pragma unroll
            for (int off = 16; off; off >>= 1)
                mx = fmaxf(mx, __shfl_xor_sync(0xffffffffu, mx, off));
            float sum = 0.f;
#pragma unroll
            for (int i = 0; i < 8; i++) {
                float e = (offs[i] >= 0) ? __expf(vals[i] - mx) : 0.f;
                vals[i] = e;
                sum += e;
            }
#pragma unroll
            for (int off = 16; off; off >>= 1)
                sum += __shfl_xor_sync(0xffffffffu, sum, off);
            const float inv = 1.0f / sum;
#pragma unroll
            for (int i = 0; i < 8; i++)
                if (offs[i] >= 0) arow[offs[i]] = vals[i] * inv;
        }
    }
    __syncthreads();

    // ---- write attn probabilities ----
    if (attn_out) {
        float* ao = attn_out + (size_t)nh * WS2 * HW;
        for (int idx = t; idx < WS2 * TPIX; idx += 256) {
            int px = idx & 31, s = idx >> 5;
            int off = (s / WS) * 16 + (s % WS);
            int pgl = (ty0 + (px >> 3)) * WDIM + tx0 + (px & 7);
            ao[s * HW + pgl] = atsm[px * ASTR + off];
        }
    }

    // ---- output: sliding-window regs; scatter into A-fragments ----
    {
        const int c    = t & 31;
        const int warp = t >> 5;
        const int py   = warp & 3;
        const int half = warp >> 2;
        const int kh0  = half ? 8 : 0;
        const int kh1  = half ? 15 : 8;
        const float* rvh = g_rvT + (size_t)h * WS2 * HDim;

        float acc[TW];
#pragma unroll
        for (int i = 0; i < TW; i++) acc[i] = 0.f;

        for (int kh = kh0; kh < kh1; kh++) {
            const int hy = py + kh;
            float vreg[HC];
#pragma unroll
            for (int x = 0; x < HC; x++)
                vreg[x] = vsm[(hy * HC + x) * KSTR + c];
            float rreg[WS];
#pragma unroll
            for (int kw = 0; kw < WS; kw++)
                rreg[kw] = rvh[(kh * WS + kw) * HDim + c];

#pragma unroll
            for (int pxx = 0; pxx < TW; pxx++) {
                const float* arow = &atsm[(py * TW + pxx) * ASTR + kh * 16];
                float4 a0 = *(const float4*)(arow);
                float4 a1 = *(const float4*)(arow + 4);
                float4 a2 = *(const float4*)(arow + 8);
                float4 a3 = *(const float4*)(arow + 12);
                float av[15] = {a0.x, a0.y, a0.z, a0.w, a1.x, a1.y, a1.z, a1.w,
                                a2.x, a2.y, a2.z, a2.w, a3.x, a3.y, a3.z};
                float s0 = 0.f;
#pragma unroll
                for (int kw = 0; kw < WS; kw++) {
                    acc[pxx] += av[kw] * vreg[pxx + kw];
                    s0       += av[kw] * rreg[kw];
                }
                acc[pxx] += s0;
            }
        }

        if (half == 1) {
#pragma unroll
            for (int pxx = 0; pxx < TW; pxx++)
                sPart[(py * TW + pxx) * 32 + c] = acc[pxx];
        }
        __syncthreads();
        if (half == 0) {
            const int kglobal = h * 32 + c;
            const int k16  = kglobal >> 4;
            const int w16  = kglobal & 15;
            const int tigf = (w16 & 7) >> 1;
            const int jhi  = (w16 >> 3) & 1;
            uint32_t* AhiU = (uint32_t*)g_Ahi;
            uint32_t* AloU = (uint32_t*)g_Alo;
#pragma unroll
            for (int pxx = 0; pxx < TW; pxx++) {
                const int gy = ty0 + py, gx = tx0 + pxx;
                float tot = acc[pxx] + sPart[(py * TW + pxx) * 32 + c];
                float totN = __shfl_xor_sync(0xffffffffu, tot, 1);
                if ((c & 1) == 0) {
                    float hiE, loE, hiO, loO;
                    split1(tot,  hiE, loE);
                    split1(totN, hiO, loO);
                    const int m = n * HW + gy * WDIM + gx;
                    const int j = jhi * 2 + ((m >> 3) & 1);
                    const int lanef = (m & 7) * 4 + tigf;
                    const size_t u =
                        ((size_t)(3 * AFRAGS)
                         + ((size_t)(m >> 4) * 16 + k16) * 32 + lanef) * 4 + j;
                    AhiU[u] = pack2(hiE, hiO);
                    AloU[u] = pack2(loE, loO);
                }
            }
        }
    }
}

// ---------------------------------------------------------------------------
extern "C" void kernel_launch(void* const* d_in, const int* in_sizes, int n_in,
                              void* d_out, int out_size)
{
    const float* q     = (const float*)d_in[0];
    const float* k     = (const float*)d_in[1];
    const float* v     = (const float*)d_in[2];
    const float* WQ    = (const float*)d_in[3];
    const float* bQ    = (const float*)d_in[4];
    const float* WK    = (const float*)d_in[5];
    const float* bK    = (const float*)d_in[6];
    const float* WV    = (const float*)d_in[7];
    const float* bV    = (const float*)d_in[8];
    const float* Wrk   = (const float*)d_in[9];
    const float* brk   = (const float*)d_in[10];
    const float* rel_v = (const float*)d_in[11];
    const float* Wp    = (const float*)d_in[12];
    const float* bp    = (const float*)d_in[13];

    float* out = (float*)d_out;
    float* attn_out = nullptr;
    if (out_size >= OUT_ELEMS + ATTN_ELEMS)
        attn_out = out + OUT_ELEMS;

    cudaFuncSetAttribute(attn_kernel,
                         cudaFuncAttributeMaxDynamicSharedMemorySize, SMEM_ATTN);

    prep_all<<<1309, 256>>>(q, k, v, WQ, WK, WV, Wp, Wrk, rel_v);
    proj_gemm<<<dim3(64, 8, 3), 512>>>(bQ, bK, bV);
    attn_kernel<<<dim3(32, HNUM, NB), 256, SMEM_ATTN>>>(brk, attn_out);
    final_gemm<<<dim3(64, 8), 512>>>(bp, out);
}

// round 16
// speedup vs baseline: 1.1105x; 1.1105x over previous
#include <cuda_runtime.h>
#include <cuda_bf16.h>
#include <cstdint>

// ---------------------------------------------------------------------------
// MultiheadLocalAttentionV1: N=2, C=256, H=8, HD=32, 32x32 spatial,
// 15x15 window (225 taps), dilation 1, pad 7.
//
//   prep_all   : weight/qkv bf16-split fragments, T*Wrk B-fragments, rel_v^T
//   proj_gemm  : split-K x2 bf16 mma GEMM; K pre-split bf16
//   attn_kernel: MMA logits + fp32 softmax + SIMT sliding-window output
//                (zero-rel_v fast path), epilogue scatters into A-fragments
//   final_gemm : split-K x2 bf16 mma GEMM, out = ao @ Wp^T + bp
// ---------------------------------------------------------------------------

#define NB      2
#define HNUM    8
#define HDim    32
#define CCH     256
#define WDIM    32
#define HW      1024
#define WS      15
#define WS2     225
#define MAXDIS  7

#define TW      8
#define TH      4
#define TPIX    32
#define HR      (TH + 14)   // 18
#define HC      (TW + 14)   // 22
#define NHALO   (HR * HC)   // 396
#define NHALO_P 400
#define KSTR    36
#define ASTR    244
#define QSTR    33
#define KROWU   18

#define T_CONST 5.656854249492381f
#define INV_T   0.17677669529663689f

#define OUT_ELEMS  (HW * NB * CCH)
#define ATTN_ELEMS (NB * HNUM * WS2 * HW)

// attn smem layout (bytes)
#define SM_K    0
#define SM_KLO_U 7200
#define SM_A    57600
#define SM_Q    88832
#define SMEM_ATTN 93056

#define AFRAGS  65536
#define BFRAGS  16384

// -------------------------- global scratch ---------------------------------
__device__ float g_qs[NB * HNUM * HW * HDim];
__device__ float g_vp[NB * HNUM * HW * HDim];
__device__ float g_rvT[HNUM * WS2 * HDim];
__device__ uint32_t g_kbf_hi[NB * HNUM * HW * 16];
__device__ uint32_t g_kbf_lo[NB * HNUM * HW * 16];

__device__ uint4 g_Ahi[4 * AFRAGS];   // slots: 0=q 1=k 2=v 3=ao
__device__ uint4 g_Alo[4 * AFRAGS];
__device__ uint2 g_Bhi[4 * BFRAGS];   // slots: 0=WQ 1=WK 2=WV 3=Wp
__device__ uint2 g_Blo[4 * BFRAGS];

__device__ uint2 g_WrkFh[HNUM * 30 * 2 * 32];
__device__ uint2 g_WrkFl[HNUM * 30 * 2 * 32];

// ---------------------------------------------------------------------------
// helpers
// ---------------------------------------------------------------------------
__device__ __forceinline__ uint32_t pack2(float a, float b) {
    __nv_bfloat162 t = __floats2bfloat162_rn(a, b);
    return *reinterpret_cast<uint32_t*>(&t);
}
__device__ __forceinline__ void split1(float x, float& hi, float& lo) {
    hi = __bfloat162float(__float2bfloat16(x));
    lo = x - hi;
}
__device__ __forceinline__ void mma_bf16(float* acc, uint4 a, uint2 b) {
    asm volatile(
        "mma.sync.aligned.m16n8k16.row.col.f32.bf16.bf16.f32 "
        "{%0,%1,%2,%3},{%4,%5,%6,%7},{%8,%9},{%0,%1,%2,%3};\n"
        : "+f"(acc[0]), "+f"(acc[1]), "+f"(acc[2]), "+f"(acc[3])
        : "r"(a.x), "r"(a.y), "r"(a.z), "r"(a.w), "r"(b.x), "r"(b.y));
}
__device__ __forceinline__ void mma3(float* acc, uint4 ah, uint4 al,
                                     uint2 bh, uint2 bl) {
    mma_bf16(acc, ah, bh);
    mma_bf16(acc, ah, bl);
    mma_bf16(acc, al, bh);
}

// ---------------------------------------------------------------------------
// prep_all: [0,256) weights; [256,1024) q/k/v; [1024,1084) T*Wrk frags;
//           [1084,1309) rel_v transpose
// ---------------------------------------------------------------------------
__global__ __launch_bounds__(256) void prep_all(
    const float* __restrict__ q, const float* __restrict__ k,
    const float* __restrict__ v,
    const float* __restrict__ WQ, const float* __restrict__ WK,
    const float* __restrict__ WV, const float* __restrict__ Wp,
    const float* __restrict__ Wrk, const float* __restrict__ rel_v)
{
    const int b = blockIdx.x;

    if (b < 256) {
        int tid  = b * 256 + threadIdx.x;
        int lane = tid & 31;
        int k16  = (tid >> 5) & 15;
        int n8   = (tid >> 9) & 31;
        int mat  = tid >> 14;
        const float* W = (mat == 0) ? WQ : (mat == 1) ? WK : (mat == 2) ? WV : Wp;

        int g = lane >> 2, tig = lane & 3;
        int n  = n8 * 8 + g;
        int kb = k16 * 16 + 2 * tig;

        const float* r = W + (size_t)n * 256;
        float h0, l0, h1, l1, h8, l8, h9, l9;
        split1(r[kb],     h0, l0);
        split1(r[kb + 1], h1, l1);
        split1(r[kb + 8], h8, l8);
        split1(r[kb + 9], h9, l9);

        size_t idx = ((size_t)(mat * 32 + n8) * 16 + k16) * 32 + lane;
        g_Bhi[idx] = make_uint2(pack2(h0, h1), pack2(h8, h9));
        g_Blo[idx] = make_uint2(pack2(l0, l1), pack2(l8, l9));
    } else if (b < 1024) {
        int mat = (b - 256) >> 8;
        const float* src = (mat == 0) ? q : (mat == 1) ? k : v;

        int tid  = ((b - 256) & 255) * 256 + threadIdx.x;
        int lane = tid & 31;
        int k16  = (tid >> 5) & 15;
        int m16  = tid >> 9;
        int g = lane >> 2, tig = lane & 3;
        int r0 = m16 * 16 + g;
        int r1 = r0 + 8;
        int kb = k16 * 16 + 2 * tig;

        int n0 = r0 >> 10, p0 = r0 & 1023;
        int n1 = r1 >> 10, p1 = r1 & 1023;

        uint32_t hi[4], lo[4];
#pragma unroll
        for (int j = 0; j < 4; j++) {
            int row_n = (j & 1) ? n1 : n0;
            int row_p = (j & 1) ? p1 : p0;
            int kc = kb + ((j >> 1) ? 8 : 0);
            float f0 = src[((size_t)(row_n * 256 + kc)) * 1024 + row_p];
            float f1 = src[((size_t)(row_n * 256 + kc + 1)) * 1024 + row_p];
            float h0, l0, h1, l1;
            split1(f0, h0, l0);
            split1(f1, h1, l1);
            hi[j] = pack2(h0, h1);
            lo[j] = pack2(l0, l1);
        }
        size_t idx = (size_t)mat * AFRAGS + ((size_t)m16 * 16 + k16) * 32 + lane;
        g_Ahi[idx] = make_uint4(hi[0], hi[1], hi[2], hi[3]);
        g_Alo[idx] = make_uint4(lo[0], lo[1], lo[2], lo[3]);
    } else if (b < 1084) {
        int i = (b - 1024) * 256 + threadIdx.x;
        int lane = i & 31;
        int k16  = (i >> 5) & 1;
        int rest = i >> 6;
        int n8 = rest % 30;
        int h  = rest / 30;
        int g = lane >> 2, tig = lane & 3;
        int s240 = n8 * 8 + g;
        int kh = s240 >> 4, kw = s240 & 15;
        int ch = 16 * k16 + 2 * tig;

        float v0 = 0.f, v1 = 0.f, v8 = 0.f, v9 = 0.f;
        if (kw < 15) {
            const float* wr = Wrk + ((size_t)(h * WS2 + kh * WS + kw)) * HDim;
            v0 = T_CONST * wr[ch];
            v1 = T_CONST * wr[ch + 1];
            v8 = T_CONST * wr[ch + 8];
            v9 = T_CONST * wr[ch + 9];
        }
        float h0, l0, h1, l1, h8, l8, h9, l9;
        split1(v0, h0, l0); split1(v1, h1, l1);
        split1(v8, h8, l8); split1(v9, h9, l9);
        size_t idx = ((size_t)(h * 30 + n8) * 2 + k16) * 32 + lane;
        g_WrkFh[idx] = make_uint2(pack2(h0, h1), pack2(h8, h9));
        g_WrkFl[idx] = make_uint2(pack2(l0, l1), pack2(l8, l9));
    } else {
        int i = (b - 1084) * 256 + threadIdx.x;
        if (i < HNUM * WS2 * HDim) {
            int c = i & 31;
            int s = (i >> 5) % WS2;
            int h = i / (WS2 * HDim);
            g_rvT[i] = rel_v[(h * HDim + c) * WS2 + s];
        }
    }
}

// ---------------------------------------------------------------------------
// GEMM half-core: warp computes 16m x 16n over 8 k16 steps starting at k0.
// ---------------------------------------------------------------------------
__device__ __forceinline__ void gemm_core8(
    const uint4* __restrict__ Ahi, const uint4* __restrict__ Alo,
    const uint2* __restrict__ Bhi, const uint2* __restrict__ Blo,
    int m16, int n8b, int lane, int k0, float acc[2][4])
{
#pragma unroll 4
    for (int kk = 0; kk < 8; kk++) {
        const int k16 = k0 + kk;
        uint4 ah = Ahi[((size_t)m16 * 16 + k16) * 32 + lane];
        uint4 al = Alo[((size_t)m16 * 16 + k16) * 32 + lane];
#pragma unroll
        for (int nt = 0; nt < 2; nt++) {
            size_t bi = ((size_t)(n8b + nt) * 16 + k16) * 32 + lane;
            mma3(acc[nt], ah, al, Bhi[bi], Blo[bi]);
        }
    }
}

// ---------------------------------------------------------------------------
// proj_gemm: split-K x2. grid (64, 8, 3), 256 threads (4 tile x 2 khalf).
// ---------------------------------------------------------------------------
__global__ __launch_bounds__(256) void proj_gemm(
    const float* __restrict__ bQ, const float* __restrict__ bK,
    const float* __restrict__ bV)
{
    __shared__ float red[4][8][32];

    const int mat  = blockIdx.z;
    const int t    = threadIdx.x;
    const int warp = t >> 5;
    const int lane = t & 31;
    const int tile  = warp & 3;
    const int khalf = warp >> 2;
    const int m16  = blockIdx.x * 2 + (tile & 1);
    const int n8b  = (blockIdx.y * 2 + (tile >> 1)) * 2;

    const uint4* Ahi = g_Ahi + (size_t)mat * AFRAGS;
    const uint4* Alo = g_Alo + (size_t)mat * AFRAGS;
    const uint2* Bhi = g_Bhi + (size_t)mat * BFRAGS;
    const uint2* Blo = g_Blo + (size_t)mat * BFRAGS;

    float acc[2][4];
#pragma unroll
    for (int i = 0; i < 2; i++)
#pragma unroll
        for (int j = 0; j < 4; j++) acc[i][j] = 0.f;

    gemm_core8(Ahi, Alo, Bhi, Blo, m16, n8b, lane, khalf * 8, acc);

    if (khalf == 1) {
#pragma unroll
        for (int i = 0; i < 2; i++)
#pragma unroll
            for (int j = 0; j < 4; j++)
                red[tile][i * 4 + j][lane] = acc[i][j];
    }
    __syncthreads();
    if (khalf == 0) {
#pragma unroll
        for (int i = 0; i < 2; i++)
#pragma unroll
            for (int j = 0; j < 4; j++)
                acc[i][j] += red[tile][i * 4 + j][lane];

        const float* b = (mat == 0) ? bQ : (mat == 1) ? bK : bV;
        const int g = lane >> 2, tig = lane & 3;
        const int r0 = m16 * 16 + g;
#pragma unroll
        for (int nt = 0; nt < 2; nt++) {
            const int o0 = (n8b + nt) * 8 + 2 * tig;
            const int h = o0 >> 5, hd = o0 & 31;
            const float b0 = b[o0], b1 = b[o0 + 1];
#pragma unroll
            for (int rr = 0; rr < 2; rr++) {
                const int r = r0 + rr * 8;
                const int n_b = r >> 10, p = r & 1023;
                float vx = acc[nt][rr * 2]     + b0;
                float vy = acc[nt][rr * 2 + 1] + b1;
                if (mat == 0) {
                    float2 val = make_float2(vx * INV_T, vy * INV_T);
                    *(float2*)&g_qs[((size_t)(n_b * HNUM + h) * HW + p) * HDim + hd] = val;
                } else if (mat == 1) {
                    float hx, lx, hy, ly;
                    split1(vx, hx, lx);
                    split1(vy, hy, ly);
                    size_t u = ((size_t)(n_b * HNUM + h) * HW + p) * 16 + (hd >> 1);
                    g_kbf_hi[u] = pack2(hx, hy);
                    g_kbf_lo[u] = pack2(lx, ly);
                } else {
                    float2 val = make_float2(vx, vy);
                    *(float2*)&g_vp[((size_t)(n_b * HNUM + h) * HW + p) * HDim + hd] = val;
                }
            }
        }
    }
}

// ---------------------------------------------------------------------------
// final_gemm: split-K x2. grid (64, 8), 256 threads.
// ---------------------------------------------------------------------------
__global__ __launch_bounds__(256) void final_gemm(
    const float* __restrict__ bp, float* __restrict__ out)
{
    __shared__ float red[4][8][32];

    const int t    = threadIdx.x;
    const int warp = t >> 5;
    const int lane = t & 31;
    const int tile  = warp & 3;
    const int khalf = warp >> 2;
    const int m16  = blockIdx.x * 2 + (tile & 1);
    const int n8b  = (blockIdx.y * 2 + (tile >> 1)) * 2;

    const uint4* Ahi = g_Ahi + (size_t)3 * AFRAGS;
    const uint4* Alo = g_Alo + (size_t)3 * AFRAGS;
    const uint2* Bhi = g_Bhi + (size_t)3 * BFRAGS;
    const uint2* Blo = g_Blo + (size_t)3 * BFRAGS;

    float acc[2][4];
#pragma unroll
    for (int i = 0; i < 2; i++)
#pragma unroll
        for (int j = 0; j < 4; j++) acc[i][j] = 0.f;

    gemm_core8(Ahi, Alo, Bhi, Blo, m16, n8b, lane, khalf * 8, acc);

    if (khalf == 1) {
#pragma unroll
        for (int i = 0; i < 2; i++)
#pragma unroll
            for (int j = 0; j < 4; j++)
                red[tile][i * 4 + j][lane] = acc[i][j];
    }
    __syncthreads();
    if (khalf == 0) {
#pragma unroll
        for (int i = 0; i < 2; i++)
#pragma unroll
            for (int j = 0; j < 4; j++)
                acc[i][j] += red[tile][i * 4 + j][lane];

        const int g = lane >> 2, tig = lane & 3;
        const int r0 = m16 * 16 + g;
#pragma unroll
        for (int nt = 0; nt < 2; nt++) {
            const int o0 = (n8b + nt) * 8 + 2 * tig;
            const float b0 = bp[o0], b1 = bp[o0 + 1];
#pragma unroll
            for (int rr = 0; rr < 2; rr++) {
                const int r = r0 + rr * 8;
                const int n_b = r >> 10, p = r & 1023;
                float2 val;
                val.x = acc[nt][rr * 2]     + b0;
                val.y = acc[nt][rr * 2 + 1] + b1;
                *(float2*)&out[((size_t)p * NB + n_b) * CCH + o0] = val;
            }
        }
    }
}

// ---------------------------------------------------------------------------
// attn_kernel: grid (32 tiles, 8 heads, 2 batch), 256 threads (8 warps).
// ---------------------------------------------------------------------------
extern __shared__ char smc[];

__global__ __launch_bounds__(256) void attn_kernel(
    const float* __restrict__ brk, float* __restrict__ attn_out)
{
    const int h = blockIdx.y;
    const int n = blockIdx.z;
    const int tileIdx = blockIdx.x;
    const int tx0 = (tileIdx & 3) * TW;
    const int ty0 = (tileIdx >> 2) * TH;
    const int t = threadIdx.x;
    const int w = t >> 5;
    const int lane = t & 31;
    const int g = lane >> 2, tig = lane & 3;
    const int nh = n * HNUM + h;

    __shared__ int s_rvnz;

    uint32_t* kHiU = (uint32_t*)(smc + SM_K);
    uint32_t* kLoU = kHiU + SM_KLO_U;
    float*    vsm  = (float*)(smc + SM_K);
    float*    atsm = (float*)(smc + SM_A);
    float*    sQ   = (float*)(smc + SM_Q);
    float*    sPart = sQ;

    const float* rvh = g_rvT + (size_t)h * WS2 * HDim;

    if (t == 0) s_rvnz = 0;

    for (int idx = t; idx < TPIX * 32; idx += 256) {
        int px = idx >> 5, c = idx & 31;
        int gp = (ty0 + (px >> 3)) * WDIM + tx0 + (px & 7);
        sQ[px * QSTR + c] = g_qs[((size_t)nh * HW + gp) * HDim + c];
    }
    {
        const uint32_t* kh_hi = g_kbf_hi + (size_t)nh * HW * 16;
        const uint32_t* kh_lo = g_kbf_lo + (size_t)nh * HW * 16;
        for (int idx = t; idx < NHALO_P * 16; idx += 256) {
            int hp = idx >> 4, c2 = idx & 15;
            uint32_t vh = 0, vl = 0;
            if (hp < NHALO) {
                int hy = hp / HC, hx = hp - hy * HC;
                int gy = ty0 - MAXDIS + hy, gx = tx0 - MAXDIS + hx;
                if ((unsigned)gy < 32u && (unsigned)gx < 32u) {
                    size_t off = (size_t)(gy * WDIM + gx) * 16 + c2;
                    vh = kh_hi[off];
                    vl = kh_lo[off];
                }
            }
            kHiU[hp * KROWU + c2] = vh;
            kLoU[hp * KROWU + c2] = vl;
        }
    }
    __syncthreads();

    // ---- scan rel_v^T slice for nonzero (fast path detect) ----
    {
        const float4* rv4 = (const float4*)rvh;   // 1800 float4
        int nz = 0;
        for (int i = t; i < (WS2 * HDim) / 4; i += 256) {
            float4 v = rv4[i];
            nz |= (v.x != 0.f) | (v.y != 0.f) | (v.z != 0.f) | (v.w != 0.f);
        }
        if (nz) s_rvnz = 1;   // benign race: all writers store 1
    }

    // ---- build Q A-fragments: 2 m16 x 2 k16 ----
    uint4 aQh[2][2], aQl[2][2];
#pragma unroll
    for (int m16 = 0; m16 < 2; m16++) {
#pragma unroll
        for (int k16 = 0; k16 < 2; k16++) {
            int rb = m16 * 16 + g;
            int kb = 16 * k16 + 2 * tig;
            float v00 = sQ[rb * QSTR + kb],            v01 = sQ[rb * QSTR + kb + 1];
            float v10 = sQ[(rb + 8) * QSTR + kb],      v11 = sQ[(rb + 8) * QSTR + kb + 1];
            float v08 = sQ[rb * QSTR + kb + 8],        v09 = sQ[rb * QSTR + kb + 9];
            float v18 = sQ[(rb + 8) * QSTR + kb + 8],  v19 = sQ[(rb + 8) * QSTR + kb + 9];
            float h00,l00,h01,l01,h10,l10,h11,l11,h08,l08,h09,l09,h18,l18,h19,l19;
            split1(v00,h00,l00); split1(v01,h01,l01);
            split1(v10,h10,l10); split1(v11,h11,l11);
            split1(v08,h08,l08); split1(v09,h09,l09);
            split1(v18,h18,l18); split1(v19,h19,l19);
            aQh[m16][k16] = make_uint4(pack2(h00,h01), pack2(h10,h11),
                                       pack2(h08,h09), pack2(h18,h19));
            aQl[m16][k16] = make_uint4(pack2(l00,l01), pack2(l10,l11),
                                       pack2(l08,l09), pack2(l18,l19));
        }
    }

    // ---- phase R: rel logits GEMM -> atsm ----
    for (int n8 = w; n8 < 30; n8 += 8) {
        float acc[2][4];
#pragma unroll
        for (int i = 0; i < 2; i++)
#pragma unroll
            for (int j = 0; j < 4; j++) acc[i][j] = 0.f;
#pragma unroll
        for (int k16 = 0; k16 < 2; k16++) {
            size_t bi = ((size_t)(h * 30 + n8) * 2 + k16) * 32 + lane;
            uint2 bh = g_WrkFh[bi];
            uint2 bl = g_WrkFl[bi];
            mma3(acc[0], aQh[0][k16], aQl[0][k16], bh, bl);
            mma3(acc[1], aQh[1][k16], aQl[1][k16], bh, bl);
        }
        const int c0 = n8 * 8 + 2 * tig;
        const int kh = c0 >> 4, kw = c0 & 15;
        float bb0 = (kw < 15) ? brk[h * WS2 + kh * WS + kw] : 0.f;
        float bb1 = (kw < 14) ? brk[h * WS2 + kh * WS + kw + 1] : 0.f;
#pragma unroll
        for (int m16 = 0; m16 < 2; m16++) {
            const int rb = m16 * 16 + g;
            atsm[rb * ASTR + c0]           = acc[m16][0] + bb0;
            atsm[rb * ASTR + c0 + 1]       = acc[m16][1] + bb1;
            atsm[(rb + 8) * ASTR + c0]     = acc[m16][2] + bb0;
            atsm[(rb + 8) * ASTR + c0 + 1] = acc[m16][3] + bb1;
        }
    }
    __syncthreads();

    // ---- phase S: dense QK GEMM + banded scatter ----
    for (int n8 = w; n8 < 50; n8 += 8) {
        float acc[2][4];
#pragma unroll
        for (int i = 0; i < 2; i++)
#pragma unroll
            for (int j = 0; j < 4; j++) acc[i][j] = 0.f;
#pragma unroll
        for (int k16 = 0; k16 < 2; k16++) {
            int bi = (n8 * 8 + g) * KROWU + 8 * k16 + tig;
            uint2 bh = make_uint2(kHiU[bi], kHiU[bi + 4]);
            uint2 bl = make_uint2(kLoU[bi], kLoU[bi + 4]);
            mma3(acc[0], aQh[0][k16], aQl[0][k16], bh, bl);
            mma3(acc[1], aQh[1][k16], aQl[1][k16], bh, bl);
        }
        const int c0 = n8 * 8 + 2 * tig;
#pragma unroll
        for (int m16 = 0; m16 < 2; m16++) {
#pragma unroll
            for (int j = 0; j < 4; j++) {
                const int row = m16 * 16 + g + ((j >> 1) ? 8 : 0);
                const int cc  = c0 + (j & 1);
                if (cc < NHALO) {
                    const int hy = cc / HC, hx = cc - hy * HC;
                    const int py = row >> 3, pxx = row & 7;
                    const int kh = hy - py, kw = hx - pxx;
                    if ((unsigned)kh < 15u && (unsigned)kw < 15u) {
                        const int gy = ty0 + hy - MAXDIS;
                        const int gx = tx0 + hx - MAXDIS;
                        const int idx = row * ASTR + kh * 16 + kw;
                        float a = atsm[idx] + acc[m16][j];
                        if (!((unsigned)gy < 32u && (unsigned)gx < 32u))
                            a -= 1e8f;
                        atsm[idx] = a;
                    }
                }
            }
        }
    }
    __syncthreads();

    // ---- load V fp32 (overwrites K region) ----
    for (int i4 = t; i4 < NHALO * 8; i4 += 256) {
        int hp = i4 >> 3, c4 = (i4 & 7) * 4;
        int hy = hp / HC, hx = hp - hy * HC;
        int gy = ty0 - MAXDIS + hy, gx = tx0 - MAXDIS + hx;
        float4 vv = make_float4(0.f, 0.f, 0.f, 0.f);
        if ((unsigned)gy < 32u && (unsigned)gx < 32u)
            vv = *(const float4*)&g_vp[((size_t)nh * HW + gy * WDIM + gx) * HDim + c4];
        *(float4*)&vsm[hp * KSTR + c4] = vv;
    }

    // ---- softmax ----
    {
#pragma unroll
        for (int pp = 0; pp < 4; pp++) {
            const int px = w * 4 + pp;
            float* arow = &atsm[px * ASTR];
            if (lane < 15) arow[lane * 16 + 15] = 0.f;
            float vals[8];
            int   offs[8];
            float mx = -3.4e38f;
#pragma unroll
            for (int i = 0; i < 8; i++) {
                int s = lane + 32 * i;
                if (s < WS2) {
                    offs[i] = (s / WS) * 16 + (s % WS);
                    vals[i] = arow[offs[i]];
                } else { offs[i] = -1; vals[i] = -3.4e38f; }
                mx = fmaxf(mx, vals[i]);
            }
#pragma unroll
            for (int off = 16; off; off >>= 1)
                mx = fmaxf(mx, __shfl_xor_sync(0xffffffffu, mx, off));
            float sum = 0.f;
#pragma unroll
            for (int i = 0; i < 8; i++) {
                float e = (offs[i] >= 0) ? __expf(vals[i] - mx) : 0.f;
                vals[i] = e;
                sum += e;
            }
#pragma unroll
            for (int off = 16; off; off >>= 1)
                sum += __shfl_xor_sync(0xffffffffu, sum, off);
            const float inv = 1.0f / sum;
#pragma unroll
            for (int i = 0; i < 8; i++)
                if (offs[i] >= 0) arow[offs[i]] = vals[i] * inv;
        }
    }
    __syncthreads();

    // ---- write attn probabilities ----
    if (attn_out) {
        float* ao = attn_out + (size_t)nh * WS2 * HW;
        for (int idx = t; idx < WS2 * TPIX; idx += 256) {
            int px = idx & 31, s = idx >> 5;
            int off = (s / WS) * 16 + (s % WS);
            int pgl = (ty0 + (px >> 3)) * WDIM + tx0 + (px & 7);
            ao[s * HW + pgl] = atsm[px * ASTR + off];
        }
    }

    // ---- output: sliding-window regs; scatter into A-fragments ----
    {
        const int c    = t & 31;
        const int warp = t >> 5;
        const int py   = warp & 3;
        const int half = warp >> 2;
        const int kh0  = half ? 8 : 0;
        const int kh1  = half ? 15 : 8;
        const bool rvnz = (s_rvnz != 0);

        float acc[TW];
#pragma unroll
        for (int i = 0; i < TW; i++) acc[i] = 0.f;

        if (rvnz) {
            for (int kh = kh0; kh < kh1; kh++) {
                const int hy = py + kh;
                float vreg[HC];
#pragma unroll
                for (int x = 0; x < HC; x++)
                    vreg[x] = vsm[(hy * HC + x) * KSTR + c];
                float rreg[WS];
#pragma unroll
                for (int kw = 0; kw < WS; kw++)
                    rreg[kw] = rvh[(kh * WS + kw) * HDim + c];

#pragma unroll
                for (int pxx = 0; pxx < TW; pxx++) {
                    const float* arow = &atsm[(py * TW + pxx) * ASTR + kh * 16];
                    float4 a0 = *(const float4*)(arow);
                    float4 a1 = *(const float4*)(arow + 4);
                    float4 a2 = *(const float4*)(arow + 8);
                    float4 a3 = *(const float4*)(arow + 12);
                    float av[15] = {a0.x, a0.y, a0.z, a0.w, a1.x, a1.y, a1.z, a1.w,
                                    a2.x, a2.y, a2.z, a2.w, a3.x, a3.y, a3.z};
                    float s0 = 0.f;
#pragma unroll
                    for (int kw = 0; kw < WS; kw++) {
                        acc[pxx] += av[kw] * vreg[pxx + kw];
                        s0       += av[kw] * rreg[kw];
                    }
                    acc[pxx] += s0;
                }
            }
        } else {
            // rel_v == 0 fast path: V stream only
            for (int kh = kh0; kh < kh1; kh++) {
                const int hy = py + kh;
                float vreg[HC];
#pragma unroll
                for (int x = 0; x < HC; x++)
                    vreg[x] = vsm[(hy * HC + x) * KSTR + c];

#pragma unroll
                for (int pxx = 0; pxx < TW; pxx++) {
                    const float* arow = &atsm[(py * TW + pxx) * ASTR + kh * 16];
                    float4 a0 = *(const float4*)(arow);
                    float4 a1 = *(const float4*)(arow + 4);
                    float4 a2 = *(const float4*)(arow + 8);
                    float4 a3 = *(const float4*)(arow + 12);
                    float av[15] = {a0.x, a0.y, a0.z, a0.w, a1.x, a1.y, a1.z, a1.w,
                                    a2.x, a2.y, a2.z, a2.w, a3.x, a3.y, a3.z};
#pragma unroll
                    for (int kw = 0; kw < WS; kw++)
                        acc[pxx] += av[kw] * vreg[pxx + kw];
                }
            }
        }

        if (half == 1) {
#pragma unroll
            for (int pxx = 0; pxx < TW; pxx++)
                sPart[(py * TW + pxx) * 32 + c] = acc[pxx];
        }
        __syncthreads();
        if (half == 0) {
            const int kglobal = h * 32 + c;
            const int k16  = kglobal >> 4;
            const int w16  = kglobal & 15;
            const int tigf = (w16 & 7) >> 1;
            const int jhi  = (w16 >> 3) & 1;
            uint32_t* AhiU = (uint32_t*)g_Ahi;
            uint32_t* AloU = (uint32_t*)g_Alo;
#pragma unroll
            for (int pxx = 0; pxx < TW; pxx++) {
                const int gy = ty0 + py, gx = tx0 + pxx;
                float tot = acc[pxx] + sPart[(py * TW + pxx) * 32 + c];
                float totN = __shfl_xor_sync(0xffffffffu, tot, 1);
                if ((c & 1) == 0) {
                    float hiE, loE, hiO, loO;
                    split1(tot,  hiE, loE);
                    split1(totN, hiO, loO);
                    const int m = n * HW + gy * WDIM + gx;
                    const int j = jhi * 2 + ((m >> 3) & 1);
                    const int lanef = (m & 7) * 4 + tigf;
                    const size_t u =
                        ((size_t)(3 * AFRAGS)
                         + ((size_t)(m >> 4) * 16 + k16) * 32 + lanef) * 4 + j;
                    AhiU[u] = pack2(hiE, hiO);
                    AloU[u] = pack2(loE, loO);
                }
            }
        }
    }
}

// ---------------------------------------------------------------------------
extern "C" void kernel_launch(void* const* d_in, const int* in_sizes, int n_in,
                              void* d_out, int out_size)
{
    const float* q     = (const float*)d_in[0];
    const float* k     = (const float*)d_in[1];
    const float* v     = (const float*)d_in[2];
    const float* WQ    = (const float*)d_in[3];
    const float* bQ    = (const float*)d_in[4];
    const float* WK    = (const float*)d_in[5];
    const float* bK    = (const float*)d_in[6];
    const float* WV    = (const float*)d_in[7];
    const float* bV    = (const float*)d_in[8];
    const float* Wrk   = (const float*)d_in[9];
    const float* brk   = (const float*)d_in[10];
    const float* rel_v = (const float*)d_in[11];
    const float* Wp    = (const float*)d_in[12];
    const float* bp    = (const float*)d_in[13];

    float* out = (float*)d_out;
    float* attn_out = nullptr;
    if (out_size >= OUT_ELEMS + ATTN_ELEMS)
        attn_out = out + OUT_ELEMS;

    cudaFuncSetAttribute(attn_kernel,
                         cudaFuncAttributeMaxDynamicSharedMemorySize, SMEM_ATTN);

    prep_all<<<1309, 256>>>(q, k, v, WQ, WK, WV, Wp, Wrk, rel_v);
    proj_gemm<<<dim3(64, 8, 3), 256>>>(bQ, bK, bV);
    attn_kernel<<<dim3(32, HNUM, NB), 256, SMEM_ATTN>>>(brk, attn_out);
    final_gemm<<<dim3(64, 8), 256>>>(bp, out);
}